// round 10
// baseline (speedup 1.0000x reference)
#include <cuda_runtime.h>
#include <cuda_bf16.h>

#define Bn   8
#define Cn   256
#define Gn   32
#define Hn   56
#define Wn   56
#define HWn  3136        // 56*56
#define QW   14          // float4 quads per row
#define ROWS 4           // output rows per block
#define NCH  2           // channels per thread
#define BTH  224         // 4 chan-pairs * ROWS * QW
#define NBLK (Bn*Gn*(Hn/ROWS))   // 3584

__device__ __forceinline__ void cp_async4(unsigned smem, const float* g) {
    asm volatile("cp.async.ca.shared.global [%0], [%1], 4;" :: "r"(smem), "l"(g));
}

__global__ __launch_bounds__(BTH, 4)
void SKA_20950850470021_kernel(const float* __restrict__ x,
                               const float* __restrict__ w,
                               float* __restrict__ out) {
    __shared__ float sw[9 * ROWS * Wn];   // 8064 B

    const int tid = threadIdx.x;
    const int bid = blockIdx.x;
    const int ht = bid % (Hn / ROWS);
    const int g  = (bid / (Hn / ROWS)) % Gn;
    const int b  = bid / ((Hn / ROWS) * Gn);
    const int h0 = ht * ROWS;

    const int q  = tid % QW;               // q innermost: lane-1 <=> q-1
    const int r  = (tid / QW) % ROWS;
    const int jp = tid / (QW * ROWS);      // 0..3 channel-pair
    const int h  = h0 + r;
    const int w0 = q * 4;
    const int lane = tid & 31;

    const float hasLf = (q > 0) ? 1.f : 0.f;
    const float hasRf = (q < QW - 1) ? 1.f : 0.f;
    const float fv[3] = { (h > 0) ? 1.f : 0.f, 1.f, (h < Hn - 1) ? 1.f : 0.f };
    const int roff[3] = { (h > 0) ? -Wn : 0, 0, (h < Hn - 1) ? Wn : 0 };
    const bool needL = (lane == 0)  && (q > 0);
    const bool needR = (lane == 31) && (q < QW - 1);

    // ---------- front-batch x: 6 center quads + warp-boundary fixups ----------
    const int base = (b * Cn + g) * HWn + h * Wn + w0;
    float4 cen[NCH][3];
    float  lfx[NCH][3];
    float  rfx[NCH][3];
#pragma unroll
    for (int j = 0; j < NCH; ++j) {
        const float* xc = x + base + (jp * NCH + j) * Gn * HWn;
#pragma unroll
        for (int rr = 0; rr < 3; ++rr) {
            const float* xr = xc + roff[rr];
            cen[j][rr] = *reinterpret_cast<const float4*>(xr);
            lfx[j][rr] = needL ? xr[-1] : 0.f;
            rfx[j][rr] = needR ? xr[4]  : 0.f;
        }
    }

    // ---------- weights stream GMEM->SMEM via cp.async (no register transit) ----------
    {
        const float* wg = w + ((b * Gn + g) * 9) * HWn + h0 * Wn;
        unsigned sbase = (unsigned)__cvta_generic_to_shared(sw);
#pragma unroll
        for (int k = 0; k < 9; ++k)
            cp_async4(sbase + (k * (ROWS * Wn) + tid) * 4, wg + k * HWn + tid);
        asm volatile("cp.async.commit_group;");
    }

    // ---------- halo via warp shuffle (overlaps cp.async flight) ----------
    float lf[NCH][3], rf[NCH][3];
#pragma unroll
    for (int j = 0; j < NCH; ++j)
#pragma unroll
        for (int rr = 0; rr < 3; ++rr) {
            float lv = __shfl_up_sync(0xFFFFFFFFu, cen[j][rr].w, 1);
            float rv = __shfl_down_sync(0xFFFFFFFFu, cen[j][rr].x, 1);
            if (lane == 0)  lv = lfx[j][rr];
            if (lane == 31) rv = rfx[j][rr];
            lf[j][rr] = lv * hasLf;   // zeros borders and cross-row shuffle garbage
            rf[j][rr] = rv * hasRf;
        }

    asm volatile("cp.async.wait_group 0;");
    __syncthreads();

    // ---------- compute: weights from smem, row validity folded in ----------
    float4 acc[NCH];
#pragma unroll
    for (int j = 0; j < NCH; ++j) acc[j] = make_float4(0.f, 0.f, 0.f, 0.f);

    const int swofs = r * Wn + w0;
#pragma unroll
    for (int rr = 0; rr < 3; ++rr) {
        float4 wk0 = *reinterpret_cast<const float4*>(&sw[(rr * 3 + 0) * (ROWS * Wn) + swofs]);
        float4 wk1 = *reinterpret_cast<const float4*>(&sw[(rr * 3 + 1) * (ROWS * Wn) + swofs]);
        float4 wk2 = *reinterpret_cast<const float4*>(&sw[(rr * 3 + 2) * (ROWS * Wn) + swofs]);
        const float s = fv[rr];
        wk0.x *= s; wk0.y *= s; wk0.z *= s; wk0.w *= s;
        wk1.x *= s; wk1.y *= s; wk1.z *= s; wk1.w *= s;
        wk2.x *= s; wk2.y *= s; wk2.z *= s; wk2.w *= s;
#pragma unroll
        for (int j = 0; j < NCH; ++j) {
            const float4 c = cen[j][rr];
            acc[j].x += lf[j][rr] * wk0.x + c.x * wk1.x + c.y * wk2.x;
            acc[j].y += c.x * wk0.y + c.y * wk1.y + c.z * wk2.y;
            acc[j].z += c.y * wk0.z + c.z * wk1.z + c.w * wk2.z;
            acc[j].w += c.z * wk0.w + c.w * wk1.w + rf[j][rr] * wk2.w;
        }
    }

#pragma unroll
    for (int j = 0; j < NCH; ++j)
        *reinterpret_cast<float4*>(out + base + (jp * NCH + j) * Gn * HWn) = acc[j];
}

extern "C" void kernel_launch(void* const* d_in, const int* in_sizes, int n_in,
                              void* d_out, int out_size) {
    const float* x = (const float*)d_in[0];   // (8,256,56,56)
    const float* w = (const float*)d_in[1];   // (8,32,9,56,56)
    float* out = (float*)d_out;               // (8,256,56,56)

    SKA_20950850470021_kernel<<<NBLK, BTH>>>(x, w, out);
}

// round 11
// speedup vs baseline: 1.1369x; 1.1369x over previous
#include <cuda_runtime.h>
#include <cuda_bf16.h>

#define Bn   8
#define Cn   256
#define Gn   32
#define Hn   56
#define Wn   56
#define HWn  3136        // 56*56
#define QW   14          // float4 quads per row
#define NPART 4          // channel-pairs per (b,g,h,q)
#define NCH   2          // channels per thread
#define TOTAL_THREADS (Bn*Gn*Hn*QW*NPART)   // 802816

__device__ __forceinline__ unsigned long long pol_keep() {
    unsigned long long p;
    asm("createpolicy.fractional.L2::evict_last.b64 %0, 1.0;" : "=l"(p));
    return p;
}
__device__ __forceinline__ unsigned long long pol_stream() {
    unsigned long long p;
    asm("createpolicy.fractional.L2::evict_first.b64 %0, 1.0;" : "=l"(p));
    return p;
}
__device__ __forceinline__ float4 ld_keep_f4(const float* p, unsigned long long pol) {
    float4 v;
    asm("ld.global.L2::cache_hint.v4.f32 {%0,%1,%2,%3}, [%4], %5;"
        : "=f"(v.x), "=f"(v.y), "=f"(v.z), "=f"(v.w) : "l"(p), "l"(pol));
    return v;
}
__device__ __forceinline__ float ld_keep_f(const float* p, unsigned long long pol) {
    float v;
    asm("ld.global.L2::cache_hint.f32 %0, [%1], %2;" : "=f"(v) : "l"(p), "l"(pol));
    return v;
}
__device__ __forceinline__ void st_stream_f4(float* p, float4 v, unsigned long long pol) {
    asm volatile("st.global.L2::cache_hint.v4.f32 [%0], {%1,%2,%3,%4}, %5;"
        :: "l"(p), "f"(v.x), "f"(v.y), "f"(v.z), "f"(v.w), "l"(pol) : "memory");
}

__global__ __launch_bounds__(128, 5)
void SKA_20950850470021_kernel(const float* __restrict__ x,
                               const float* __restrict__ w,
                               float* __restrict__ out) {
    int idx = blockIdx.x * blockDim.x + threadIdx.x;

    int q = idx % QW;
    int t = idx / QW;
    int h = t % Hn;
    t /= Hn;
    int g = t % Gn;
    t /= Gn;
    int b = t % Bn;
    int p = t / Bn;          // 0..3 : which pair of channels

    const unsigned long long PK = pol_keep();
    const unsigned long long PS = pol_stream();

    const int lane = threadIdx.x & 31;
    const int w0 = q * 4;
    const float hasLf = (q > 0) ? 1.f : 0.f;
    const float hasRf = (q < QW - 1) ? 1.f : 0.f;

    const float fv[3] = { (h > 0) ? 1.f : 0.f, 1.f, (h < Hn - 1) ? 1.f : 0.f };
    const int roff[3] = { (h > 0) ? -Wn : 0, 0, (h < Hn - 1) ? Wn : 0 };

    const bool needL = (lane == 0)  && (q > 0);
    const bool needR = (lane == 31) && (q < QW - 1);

    // ---------------- load phase: everything front-batched, L2-pinned ----------------
    const float* wbase = w + ((b * Gn + g) * 9) * HWn + h * Wn + w0;
    float4 wk[9];
#pragma unroll
    for (int k = 0; k < 9; ++k)
        wk[k] = ld_keep_f4(wbase + k * HWn, PK);

    const int base = (b * Cn + g) * HWn + h * Wn + w0;
    float4 cen[NCH][3];
    float  lfx[NCH][3];
    float  rfx[NCH][3];
#pragma unroll
    for (int j = 0; j < NCH; ++j) {
        const float* xc = x + base + (p * NCH + j) * Gn * HWn;
#pragma unroll
        for (int r = 0; r < 3; ++r) {
            const float* xr = xc + roff[r];
            cen[j][r] = ld_keep_f4(xr, PK);
            lfx[j][r] = needL ? ld_keep_f(xr - 1, PK) : 0.f;
            rfx[j][r] = needR ? ld_keep_f(xr + 4, PK) : 0.f;
        }
    }

    // ---------------- halo via warp shuffle (no L1 traffic) ----------------
    float lf[NCH][3], rf[NCH][3];
#pragma unroll
    for (int j = 0; j < NCH; ++j)
#pragma unroll
        for (int r = 0; r < 3; ++r) {
            float lv = __shfl_up_sync(0xFFFFFFFFu, cen[j][r].w, 1);
            float rv = __shfl_down_sync(0xFFFFFFFFu, cen[j][r].x, 1);
            if (lane == 0)  lv = lfx[j][r];
            if (lane == 31) rv = rfx[j][r];
            lf[j][r] = lv * hasLf;   // zeros borders and cross-row shuffle garbage
            rf[j][r] = rv * hasRf;
        }

    // ---------------- compute phase ----------------
#pragma unroll
    for (int k = 0; k < 9; ++k) {
        const float s = fv[k / 3];
        wk[k].x *= s; wk[k].y *= s; wk[k].z *= s; wk[k].w *= s;
    }

    float4 acc[NCH];
#pragma unroll
    for (int j = 0; j < NCH; ++j) {
        float4 a = make_float4(0.f, 0.f, 0.f, 0.f);
#pragma unroll
        for (int r = 0; r < 3; ++r) {
            const float4 wk0 = wk[r * 3 + 0];
            const float4 wk1 = wk[r * 3 + 1];
            const float4 wk2 = wk[r * 3 + 2];
            const float4 c = cen[j][r];
            a.x += lf[j][r] * wk0.x + c.x * wk1.x + c.y * wk2.x;
            a.y += c.x * wk0.y + c.y * wk1.y + c.z * wk2.y;
            a.z += c.y * wk0.z + c.z * wk1.z + c.w * wk2.z;
            a.w += c.z * wk0.w + c.w * wk1.w + rf[j][r] * wk2.w;
        }
        acc[j] = a;
    }

#pragma unroll
    for (int j = 0; j < NCH; ++j)
        st_stream_f4(out + base + (p * NCH + j) * Gn * HWn, acc[j], PS);
}

extern "C" void kernel_launch(void* const* d_in, const int* in_sizes, int n_in,
                              void* d_out, int out_size) {
    const float* x = (const float*)d_in[0];   // (8,256,56,56)
    const float* w = (const float*)d_in[1];   // (8,32,9,56,56)
    float* out = (float*)d_out;               // (8,256,56,56)

    const int threads = 128;
    const int blocks = TOTAL_THREADS / threads;  // 6272
    SKA_20950850470021_kernel<<<blocks, threads>>>(x, w, out);
}